// round 16
// baseline (speedup 1.0000x reference)
#include <cuda_runtime.h>
#include <cstdint>

#define Hon 502
#define Won 502
#define NT 256
#define PB_OFF 0
#define QA_OFF 131072
#define QSZ    36864
#define SMEM_BYTES 204800

static __device__ __forceinline__ uint32_t tf(float f){
    uint32_t r; asm("cvt.rna.tf32.f32 %0, %1;" : "=r"(r) : "f"(f)); return r;
}

__global__ __launch_bounds__(NT, 1)
void corr_hmma_kernel(const float* __restrict__ pg, const float* __restrict__ qg,
                      float* __restrict__ outg)
{
    extern __shared__ __align__(16) char sm[];
    uint32_t* pB = (uint32_t*)(sm + PB_OFF);   // [h4][wb8][ks16][l32][2]
    const int tid = threadIdx.x, wb = tid >> 5, l = tid & 31;
    const int wo0 = blockIdx.x * 64, h0 = blockIdx.y * 4, b = blockIdx.z;
    const float* pbase = pg + (size_t)b * Hon * Won * 128;
    const float* qbase = qg + (size_t)b * 512 * 512 * 128;

    // ---- stage p (full K), frag-major ----
    #pragma unroll 4
    for (int i = 0; i < 64; ++i) {
        int s  = tid + i * NT;                 // 0..16383
        int hh = s >> 12, wbs = (s >> 9) & 7, ks = (s >> 5) & 15, ll = s & 31;
        int w  = wo0 + wbs * 8 + (ll >> 2); if (w > 501) w = 501;
        int hp = h0 + hh;                      if (hp > 501) hp = 501;
        int c  = ks * 8 + (ll & 3);
        const float* g = pbase + ((size_t)hp * Won + w) * 128 + c;
        uint32_t u0 = tf(g[0]), u1 = tf(g[4]);
        asm volatile("st.shared.v2.b32 [%0], {%1,%2};"
                     :: "l"((char*)&pB[s * 2]), "r"(u0), "r"(u1) : "memory");
    }

    // ---- stage q row 0 ----
    {
        uint32_t* qA = (uint32_t*)(sm + QA_OFF);
        int row = h0 + 2; if (row > 511) row = 511;
        #pragma unroll 3
        for (int i = 0; i < 18; ++i) {
            int s = tid + i * NT;              // 0..4607
            int j = s >> 9, ks = (s >> 5) & 15, ll = s & 31;
            int qc = wo0 + 2 + 8 * j + (ll >> 2); if (qc > 511) qc = 511;
            int c  = ks * 8 + (ll & 3);
            const float* g = qbase + ((size_t)row * 512 + qc) * 128 + c;
            uint32_t u0 = tf(g[0]), u1 = tf(g[4]);
            asm volatile("st.shared.v2.b32 [%0], {%1,%2};"
                         :: "l"((char*)&qA[s * 2]), "r"(u0), "r"(u1) : "memory");
        }
    }
    __syncthreads();

    const int ni_ = 2 * (l & 3), mi = l >> 2;
    const int dx0 = mi - ni_;

    for (int rr = 0; rr < 12; ++rr) {
        // stage q row rr+1 into other buffer
        if (rr < 11) {
            uint32_t* qA = (uint32_t*)(sm + QA_OFF + ((rr + 1) & 1) * QSZ);
            int row = h0 + 2 + rr + 1; if (row > 511) row = 511;
            #pragma unroll 3
            for (int i = 0; i < 18; ++i) {
                int s = tid + i * NT;
                int j = s >> 9, ks = (s >> 5) & 15, ll = s & 31;
                int qc = wo0 + 2 + 8 * j + (ll >> 2); if (qc > 511) qc = 511;
                int c  = ks * 8 + (ll & 3);
                const float* g = qbase + ((size_t)row * 512 + qc) * 128 + c;
                uint32_t u0 = tf(g[0]), u1 = tf(g[4]);
                asm volatile("st.shared.v2.b32 [%0], {%1,%2};"
                             :: "l"((char*)&qA[s * 2]), "r"(u0), "r"(u1) : "memory");
            }
        }

        // compute rr from current buffer
        const uint32_t* qA = (const uint32_t*)(sm + QA_OFF + (rr & 1) * QSZ);
        int hstart = rr - 8; if (hstart < 0) hstart = 0;
        int hend   = rr < 3 ? rr : 3;
        int nh     = hend - hstart + 1;

        float acc[4][4];
        #pragma unroll
        for (int i = 0; i < 4; ++i)
            #pragma unroll
            for (int k = 0; k < 4; ++k) acc[i][k] = 0.f;

        #pragma unroll 4
        for (int ks = 0; ks < 16; ++ks) {
            uint32_t a0, a1, a2, a3, b0, b1;
            asm volatile("ld.shared.v2.b32 {%0,%1}, [%2];"
                         : "=r"(a0), "=r"(a2)
                         : "l"((const char*)&qA[(((wb)     * 16 + ks) * 32 + l) * 2]));
            asm volatile("ld.shared.v2.b32 {%0,%1}, [%2];"
                         : "=r"(a1), "=r"(a3)
                         : "l"((const char*)&qA[(((wb + 1) * 16 + ks) * 32 + l) * 2]));
            #pragma unroll
            for (int i = 0; i < 4; ++i) {
                if (i < nh) {
                    int h = hstart + i;
                    asm volatile("ld.shared.v2.b32 {%0,%1}, [%2];"
                                 : "=r"(b0), "=r"(b1)
                                 : "l"((const char*)&pB[(((h * 8 + wb) * 16 + ks) * 32 + l) * 2]));
                    asm volatile("mma.sync.aligned.m16n8k8.row.col.f32.tf32.tf32.f32 "
                                 "{%0,%1,%2,%3},{%4,%5,%6,%7},{%8,%9},{%0,%1,%2,%3};"
                                 : "+f"(acc[i][0]), "+f"(acc[i][1]),
                                   "+f"(acc[i][2]), "+f"(acc[i][3])
                                 : "r"(a0), "r"(a1), "r"(a2), "r"(a3), "r"(b0), "r"(b1));
                }
            }
        }

        // write band
        #pragma unroll
        for (int i = 0; i < 4; ++i) {
            if (i < nh) {
                int h = hstart + i, hh = h0 + h, dy = rr - h;
                if (hh <= 501) {
                    size_t rowbase = ((size_t)(b * Hon + hh) * Won + wo0 + wb * 8);
                    int w0p = wo0 + wb * 8;
                    // (dx, ni, val): c0:(dx0,ni_), c1:(dx0-1,ni_+1), c2:(dx0+8,ni_), c3:(dx0+7,ni_+1)
                    if (dx0 >= 0 && dx0 <= 8 && w0p + ni_ <= 501)
                        outg[(rowbase + ni_) * 81 + dy * 9 + dx0] = acc[i][0];
                    if (dx0 - 1 >= 0 && dx0 - 1 <= 8 && w0p + ni_ + 1 <= 501)
                        outg[(rowbase + ni_ + 1) * 81 + dy * 9 + dx0 - 1] = acc[i][1];
                    if (dx0 + 8 <= 8 && w0p + ni_ <= 501)   // dx0+8 in range iff dx0==0
                        outg[(rowbase + ni_) * 81 + dy * 9 + dx0 + 8] = acc[i][2];
                    if (dx0 + 7 >= 0 && dx0 + 7 <= 8 && w0p + ni_ + 1 <= 501)
                        outg[(rowbase + ni_ + 1) * 81 + dy * 9 + dx0 + 7] = acc[i][3];
                }
            }
        }
        __syncthreads();
    }
}

extern "C" void kernel_launch(void* const* d_in, const int* in_sizes, int n_in,
                              void* d_out, int out_size)
{
    const float* p = (const float*)d_in[0];
    const float* q = (const float*)d_in[1];
    float* out = (float*)d_out;
    cudaFuncSetAttribute(corr_hmma_kernel,
                         cudaFuncAttributeMaxDynamicSharedMemorySize, SMEM_BYTES);
    dim3 grid(8, 126, 4);     // w-tiles, h-tiles, batch
    corr_hmma_kernel<<<grid, NT, SMEM_BYTES>>>(p, q, out);
}

// round 17
// speedup vs baseline: 1.4917x; 1.4917x over previous
#include <cuda_runtime.h>
#include <cstdint>

#define Hon 502
#define Won 502
#define NT 512
#define QSZ 36864            // 9*16*32*2*4 bytes per q-row buffer
#define PS_OFF 73728         // transient p chunk: 4h*8wb*4ks*32l*2*4 = 32768
#define SMEM_BYTES 106496

static __device__ __forceinline__ uint32_t tf(float f){
    uint32_t r; asm("cvt.rna.tf32.f32 %0, %1;" : "=r"(r) : "f"(f)); return r;
}

__global__ __launch_bounds__(NT, 1)
void corr_hmma2_kernel(const float* __restrict__ pg, const float* __restrict__ qg,
                       float* __restrict__ outg)
{
    extern __shared__ __align__(16) char sm[];
    const int tid = threadIdx.x, wid = tid >> 5, l = tid & 31;
    const int wb = wid & 7, hs = wid >> 3;
    const int wo0 = blockIdx.x * 64, h0 = blockIdx.y * 4, b = blockIdx.z;
    const float* pbase = pg + (size_t)b * Hon * Won * 128;
    const float* qbase = qg + (size_t)b * 512 * 512 * 128;

    // ---- prolog: load p fragments into registers via 4 transient smem chunks ----
    uint32_t bf[2][16][2];
    uint32_t* pS = (uint32_t*)(sm + PS_OFF);
    #pragma unroll 1
    for (int kc = 0; kc < 4; ++kc) {
        #pragma unroll
        for (int i = 0; i < 8; ++i) {
            int s = tid + i * NT;                 // 0..4095
            int hh = s >> 10, rem = s & 1023;
            int wbs = rem >> 7, ksL = (rem >> 5) & 3, ll = s & 31;
            int w  = wo0 + wbs * 8 + (ll >> 2); if (w > 501) w = 501;
            int hp = h0 + hh;                    if (hp > 501) hp = 501;
            const float* g = pbase + ((size_t)hp * Won + w) * 128 + kc * 32 + ksL * 8 + (ll & 3);
            uint32_t u0 = tf(g[0]), u1 = tf(g[4]);
            asm volatile("st.shared.v2.b32 [%0], {%1,%2};"
                         :: "l"((char*)&pS[s * 2]), "r"(u0), "r"(u1) : "memory");
        }
        __syncthreads();
        #pragma unroll
        for (int i = 0; i < 2; ++i) {
            int h = hs * 2 + i;
            #pragma unroll
            for (int ksL = 0; ksL < 4; ++ksL) {
                asm volatile("ld.shared.v2.b32 {%0,%1}, [%2];"
                             : "=r"(bf[i][kc * 4 + ksL][0]), "=r"(bf[i][kc * 4 + ksL][1])
                             : "l"((const char*)&pS[(((h * 8 + wb) * 4 + ksL) * 32 + l) * 2]));
            }
        }
        __syncthreads();
    }

    // ---- q staging helper vars: this thread owns (ks = wid, lane l), loops j ----
    const int ksq = wid;                       // 0..15
    const int qc_base = wo0 + 2 + (l >> 2);
    const int cq = ksq * 8 + (l & 3);

    // stage q row 0 into buffer 0
    {
        uint32_t* qA = (uint32_t*)sm;
        int row = h0 + 2; if (row > 511) row = 511;
        #pragma unroll
        for (int j = 0; j < 9; ++j) {
            int qc = qc_base + 8 * j; if (qc > 511) qc = 511;
            const float* g = qbase + ((size_t)row * 512 + qc) * 128 + cq;
            uint32_t u0 = tf(g[0]), u1 = tf(g[4]);
            asm volatile("st.shared.v2.b32 [%0], {%1,%2};"
                         :: "l"((char*)&qA[((j * 16 + ksq) * 32 + l) * 2]), "r"(u0), "r"(u1) : "memory");
        }
    }
    __syncthreads();

    const int ni_ = 2 * (l & 3), mi = l >> 2;
    const int dx0 = mi - ni_;

    #pragma unroll 1
    for (int rr = 0; rr < 12; ++rr) {
        // stage q row rr+1 into the other buffer (LDGs issued before compute)
        if (rr < 11) {
            uint32_t* qA = (uint32_t*)(sm + ((rr + 1) & 1) * QSZ);
            int row = h0 + 3 + rr; if (row > 511) row = 511;
            #pragma unroll
            for (int j = 0; j < 9; ++j) {
                int qc = qc_base + 8 * j; if (qc > 511) qc = 511;
                const float* g = qbase + ((size_t)row * 512 + qc) * 128 + cq;
                uint32_t u0 = tf(g[0]), u1 = tf(g[4]);
                asm volatile("st.shared.v2.b32 [%0], {%1,%2};"
                             :: "l"((char*)&qA[((j * 16 + ksq) * 32 + l) * 2]), "r"(u0), "r"(u1) : "memory");
            }
        }

        // compute rr from current buffer
        const uint32_t* qA = (const uint32_t*)(sm + (rr & 1) * QSZ);
        const int dy0 = rr - (hs * 2), dy1 = dy0 - 1;
        const bool v0 = (dy0 >= 0 && dy0 <= 8), v1 = (dy1 >= 0 && dy1 <= 8);

        if (v0 || v1) {
            float acc[2][2][4];
            #pragma unroll
            for (int i = 0; i < 2; ++i)
                #pragma unroll
                for (int p2 = 0; p2 < 2; ++p2)
                    #pragma unroll
                    for (int k = 0; k < 4; ++k) acc[i][p2][k] = 0.f;

            #pragma unroll
            for (int ks = 0; ks < 16; ++ks) {
                uint32_t a0, a1, a2, a3;
                asm volatile("ld.shared.v2.b32 {%0,%1}, [%2];"
                             : "=r"(a0), "=r"(a2)
                             : "l"((const char*)(qA + (((wb)     * 16 + ks) * 32 + l) * 2)));
                asm volatile("ld.shared.v2.b32 {%0,%1}, [%2];"
                             : "=r"(a1), "=r"(a3)
                             : "l"((const char*)(qA + (((wb + 1) * 16 + ks) * 32 + l) * 2)));
                const int p2 = ks & 1;
                if (v0)
                    asm volatile("mma.sync.aligned.m16n8k8.row.col.f32.tf32.tf32.f32 "
                                 "{%0,%1,%2,%3},{%4,%5,%6,%7},{%8,%9},{%0,%1,%2,%3};"
                                 : "+f"(acc[0][p2][0]), "+f"(acc[0][p2][1]),
                                   "+f"(acc[0][p2][2]), "+f"(acc[0][p2][3])
                                 : "r"(a0), "r"(a1), "r"(a2), "r"(a3),
                                   "r"(bf[0][ks][0]), "r"(bf[0][ks][1]));
                if (v1)
                    asm volatile("mma.sync.aligned.m16n8k8.row.col.f32.tf32.tf32.f32 "
                                 "{%0,%1,%2,%3},{%4,%5,%6,%7},{%8,%9},{%0,%1,%2,%3};"
                                 : "+f"(acc[1][p2][0]), "+f"(acc[1][p2][1]),
                                   "+f"(acc[1][p2][2]), "+f"(acc[1][p2][3])
                                 : "r"(a0), "r"(a1), "r"(a2), "r"(a3),
                                   "r"(bf[1][ks][0]), "r"(bf[1][ks][1]));
            }

            // band write
            #pragma unroll
            for (int i = 0; i < 2; ++i) {
                const bool vi = i ? v1 : v0;
                if (vi) {
                    int h = hs * 2 + i, hh = h0 + h, dy = rr - h;
                    if (hh <= 501) {
                        float c0 = acc[i][0][0] + acc[i][1][0];
                        float c1 = acc[i][0][1] + acc[i][1][1];
                        float c2 = acc[i][0][2] + acc[i][1][2];
                        float c3 = acc[i][0][3] + acc[i][1][3];
                        size_t rowbase = ((size_t)(b * Hon + hh) * Won + wo0 + wb * 8);
                        int w0p = wo0 + wb * 8;
                        if (dx0 >= 0 && dx0 <= 8 && w0p + ni_ <= 501)
                            outg[(rowbase + ni_) * 81 + dy * 9 + dx0] = c0;
                        if (dx0 - 1 >= 0 && dx0 - 1 <= 8 && w0p + ni_ + 1 <= 501)
                            outg[(rowbase + ni_ + 1) * 81 + dy * 9 + dx0 - 1] = c1;
                        if (dx0 + 8 <= 8 && w0p + ni_ <= 501)
                            outg[(rowbase + ni_) * 81 + dy * 9 + dx0 + 8] = c2;
                        if (dx0 + 7 >= 0 && dx0 + 7 <= 8 && w0p + ni_ + 1 <= 501)
                            outg[(rowbase + ni_ + 1) * 81 + dy * 9 + dx0 + 7] = c3;
                    }
                }
            }
        }
        __syncthreads();
    }
}

extern "C" void kernel_launch(void* const* d_in, const int* in_sizes, int n_in,
                              void* d_out, int out_size)
{
    const float* p = (const float*)d_in[0];
    const float* q = (const float*)d_in[1];
    float* out = (float*)d_out;
    cudaFuncSetAttribute(corr_hmma2_kernel,
                         cudaFuncAttributeMaxDynamicSharedMemorySize, SMEM_BYTES);
    dim3 grid(8, 126, 4);     // w-tiles, h-tiles, batch
    corr_hmma2_kernel<<<grid, NT, SMEM_BYTES>>>(p, q, out);
}